// round 9
// baseline (speedup 1.0000x reference)
#include <cuda_runtime.h>

typedef unsigned long long ull;

// ---------------- packed f32x2 helpers (Blackwell FFMA2 path) ----------------
__device__ __forceinline__ ull pack2(float a, float b) {
    ull r; asm("mov.b64 %0, {%1,%2};" : "=l"(r) : "f"(a), "f"(b)); return r;
}
__device__ __forceinline__ float2 unpack2(ull v) {
    float2 f; asm("mov.b64 {%0,%1}, %2;" : "=f"(f.x), "=f"(f.y) : "l"(v)); return f;
}
__device__ __forceinline__ ull ffma2(ull a, ull b, ull c) {
    ull d; asm("fma.rn.f32x2 %0, %1, %2, %3;" : "=l"(d) : "l"(a), "l"(b), "l"(c)); return d;
}
__device__ __forceinline__ ull fadd2(ull a, ull b) {
    ull d; asm("add.rn.f32x2 %0, %1, %2;" : "=l"(d) : "l"(a), "l"(b)); return d;
}
// guaranteed LDS.128 — volatile + memory clobber so it can NEVER be CSE'd
// across steps or hoisted over __syncthreads (round-8 failure mode).
__device__ __forceinline__ ulonglong2 lds128(const ull* p) {
    ulonglong2 v;
    unsigned a = (unsigned)__cvta_generic_to_shared(p);
    asm volatile("ld.shared.v2.u64 {%0,%1}, [%2];"
                 : "=l"(v.x), "=l"(v.y) : "r"(a) : "memory");
    return v;
}

// HW tanh (single MUFU op); validated rel_err ~7e-7 end-to-end
__device__ __forceinline__ float tanh_fast(float x) {
    float y; asm("tanh.approx.f32 %0, %1;" : "=f"(y) : "f"(x)); return y;
}
__device__ __forceinline__ float sig_fast(float x) {
    return fmaf(0.5f, tanh_fast(0.5f * x), 0.5f);
}
__device__ __forceinline__ float sigmoidf_acc(float x) {
    return __fdividef(1.f, 1.f + __expf(-x));
}

#define B_  256
#define S_  1024
#define F_  64
#define H_  64
#define G_  256   // 4*H

// Pair mapping: pair index p -> u = p>>1, s = p&1
//   s=0: columns (u,     u+64 ) = (z_i[u],  z_f[u])
//   s=1: columns (u+128, u+192) = (z_c[u],  z_o[u])
// xz scratch: [t][b][p] packed float2 (col c0, col c1). 268MB.
__device__ ull   g_xz[(size_t)S_ * B_ * 128];
// h scratch: [b][t][u] floats. 64MB.
__device__ float g_h[(size_t)B_ * S_ * H_];

// =====================================================================
// Kernel A: xz = x @ kernel + bias
// 1024 CTAs x 256 thr; per iter one quad (4 rows); LDS.128 x-loads.
// =====================================================================
__global__ void __launch_bounds__(256, 1) lstm_xgemm(
    const float* __restrict__ x, const float* __restrict__ kern,
    const float* __restrict__ bias)
{
    const int tid  = threadIdx.x;
    const int j    = tid & 127;
    const int half = tid >> 7;
    const int u    = j >> 1;
    const int s    = j & 1;
    const int c0   = u + (s ? 128 : 0);
    const int c1   = c0 + 64;

    ull wA[32], wB[32];
#pragma unroll
    for (int m = 0; m < 32; m++) {
        wA[m] = pack2(kern[(2 * m) * G_ + c0], kern[(2 * m + 1) * G_ + c0]);
        wB[m] = pack2(kern[(2 * m) * G_ + c1], kern[(2 * m + 1) * G_ + c1]);
    }
    const float bc0 = bias[c0], bc1 = bias[c1];

    __shared__ __align__(16) ull xpk[4][4][32];   // [slot][row][kpair] ring

    const int lr = (tid >> 5) & 3;
    const int lm = tid & 31;
    const int qbase = blockIdx.x * 64;

    float2 v = make_float2(0.f, 0.f);
    if (tid < 128) {
        float2 t0 = *(const float2*)(x + (size_t)((qbase + 0) * 4 + lr) * F_ + 2 * lm);
        xpk[0][lr][lm] = pack2(t0.x, t0.y);
        float2 t1 = *(const float2*)(x + (size_t)((qbase + 1) * 4 + lr) * F_ + 2 * lm);
        xpk[1][lr][lm] = pack2(t1.x, t1.y);
        v = *(const float2*)(x + (size_t)((qbase + 2) * 4 + lr) * F_ + 2 * lm);
    }
    __syncthreads();

#pragma unroll 4
    for (int i = 0; i < 64; i++) {
        if (tid < 128 && i + 2 < 64) {
            xpk[(i + 2) & 3][lr][lm] = pack2(v.x, v.y);
            if (i + 3 < 64)
                v = *(const float2*)(x + (size_t)((qbase + i + 3) * 4 + lr) * F_ + 2 * lm);
        }

        const ull* xa = xpk[i & 3][half];
        const ull* xb = xpk[i & 3][half + 2];
        ull a0 = 0, a1 = 0, a2 = 0, a3 = 0;
        ull b0 = 0, b1 = 0, b2 = 0, b3 = 0;
#pragma unroll
        for (int m = 0; m < 32; m += 2) {
            const ulonglong2 va = lds128(xa + m);   // LDS.128
            const ulonglong2 vb = lds128(xb + m);
            a0 = ffma2(wA[m],     va.x, a0);
            a1 = ffma2(wA[m + 1], va.y, a1);
            a2 = ffma2(wB[m],     va.x, a2);
            a3 = ffma2(wB[m + 1], va.y, a3);
            b0 = ffma2(wA[m],     vb.x, b0);
            b1 = ffma2(wA[m + 1], vb.y, b1);
            b2 = ffma2(wB[m],     vb.x, b2);
            b3 = ffma2(wB[m + 1], vb.y, b3);
        }
        const float2 sa0 = unpack2(fadd2(a0, a1));
        const float2 sa1 = unpack2(fadd2(a2, a3));
        const float2 sb0 = unpack2(fadd2(b0, b1));
        const float2 sb1 = unpack2(fadd2(b2, b3));
        const ull r0 = pack2(bc0 + sa0.x + sa0.y, bc1 + sa1.x + sa1.y);
        const ull r1 = pack2(bc0 + sb0.x + sb0.y, bc1 + sb1.x + sb1.y);

        const int n0 = (qbase + i) * 4 + half;
        const int n1 = n0 + 2;
        {
            const int bb = n0 >> 10, tt = n0 & 1023;
            g_xz[((size_t)tt * B_ + bb) * 128 + j] = r0;
        }
        {
            const int bb = n1 >> 10, tt = n1 & 1023;
            g_xz[((size_t)tt * B_ + bb) * 128 + j] = r1;
        }
        __syncthreads();
    }
}

// =====================================================================
// Kernel B: LSTM recurrence. 128 CTAs x 256 thr (2 rows/CTA, uniform
// 1 CTA/SM). Depth-8 z register ring, LDS.128 h loads, plain
// __syncthreads, h streamed to g_h for the separate head kernel.
// =====================================================================
__global__ void __launch_bounds__(256, 1) lstm_recur(
    const float* __restrict__ rec)
{
    const int tid  = threadIdx.x;
    const int p    = tid & 127;
    const int r    = tid >> 7;
    const int u    = p >> 1;
    const int s    = p & 1;
    const int brow = blockIdx.x * 2 + r;
    const int c0   = u + (s ? 128 : 0);
    const int c1   = c0 + 64;

    ull wA[32], wB[32];
#pragma unroll
    for (int m = 0; m < 32; m++) {
        wA[m] = pack2(rec[(2 * m) * G_ + c0], rec[(2 * m + 1) * G_ + c0]);
        wB[m] = pack2(rec[(2 * m) * G_ + c1], rec[(2 * m + 1) * G_ + c1]);
    }

    __shared__ __align__(16) ull hpk[2][2][32];   // [parity][row][m] = (h_2m, h_2m+1)

    if (tid < 64) hpk[1][tid >> 5][tid & 31] = 0ull;   // h(-1) = 0 at parity 1

    float c = 0.f;
    const size_t ZS = (size_t)B_ * 128;
    const ull* zp = g_xz + (size_t)brow * 128 + p;
    float* hout = g_h + (size_t)brow * S_ * H_ + u;    // [t][u] stream

    // depth-8 z prefetch ring
    ull zr[8];
#pragma unroll
    for (int d = 0; d < 8; d++) zr[d] = zp[(size_t)d * ZS];
    zp += 8 * ZS;
    __syncthreads();

#pragma unroll 8
    for (int t = 0; t < S_; t++) {
        const int  pr = (t & 1) ^ 1;            // parity holding h(t-1)
        const ull* hp = hpk[pr][r];

        const ull zcur = zr[t & 7];             // z issued 8 steps ago
        if (t + 8 < S_) zr[t & 7] = *zp;
        zp += ZS;

        // matvec: 16 broadcast LDS.128 + 64 FFMA2, 8 chains
        ull a0 = 0, a1 = 0, a2 = 0, a3 = 0;
        ull b0 = 0, b1 = 0, b2 = 0, b3 = 0;
#pragma unroll
        for (int m = 0; m < 32; m += 4) {
            const ulonglong2 h01 = lds128(hp + m);       // LDS.128
            const ulonglong2 h23 = lds128(hp + m + 2);
            a0 = ffma2(wA[m],     h01.x, a0);
            a1 = ffma2(wA[m + 1], h01.y, a1);
            a2 = ffma2(wB[m],     h01.x, a2);
            a3 = ffma2(wB[m + 1], h01.y, a3);
            b0 = ffma2(wA[m + 2], h23.x, b0);
            b1 = ffma2(wA[m + 3], h23.y, b1);
            b2 = ffma2(wB[m + 2], h23.x, b2);
            b3 = ffma2(wB[m + 3], h23.y, b3);
        }
        const float2 sa  = unpack2(fadd2(fadd2(a0, a1), fadd2(b0, b1)));
        const float2 sb  = unpack2(fadd2(fadd2(a2, a3), fadd2(b2, b3)));
        const float2 zin = unpack2(zcur);
        const float zv0 = zin.x + sa.x + sa.y;  // z_i (s=0) / z_c (s=1)
        const float zv1 = zin.y + sb.x + sb.y;  // z_f (s=0) / z_o (s=1)

        // own activations, then in-warp exchange with partner lane
        const float g0 = s ? tanh_fast(zv0) : sig_fast(zv0);
        const float g1 = sig_fast(zv1);
        const float t0 = __shfl_xor_sync(0xffffffffu, g0, 1);
        const float t1 = __shfl_xor_sync(0xffffffffu, g1, 1);

        if (s == 0) {                           // lane holds (i,f); partner sent (tc,o)
            c = fmaf(g1, c, g0 * t0);
            const float h = t1 * tanh_fast(c);
            ((float*)hpk[t & 1][r])[u] = h;     // publish h_u(t) for next step
            hout[(size_t)t * H_] = h;           // stream to gmem (off-chain STG)
        }
        __syncthreads();                        // plain BAR (floor ~7)
    }
}

// =====================================================================
// Kernel C: dense head  out[b,t] = sigmoid(h[b,t,:]·dw + db)
// One warp per output, coalesced float2 loads, shfl reduce.
// =====================================================================
__global__ void __launch_bounds__(256, 4) lstm_head(
    const float* __restrict__ dw, const float* __restrict__ db,
    float* __restrict__ out)
{
    const int lane = threadIdx.x & 31;
    const int o    = blockIdx.x * 8 + (threadIdx.x >> 5);   // output index b*S+t

    const float2 hv = *(const float2*)(g_h + (size_t)o * H_ + 2 * lane);
    const float2 wv = *(const float2*)(dw + 2 * lane);
    float pd = hv.x * wv.x + hv.y * wv.y;
#pragma unroll
    for (int off = 16; off; off >>= 1)
        pd += __shfl_xor_sync(0xffffffffu, pd, off);
    if (lane == 0)
        out[o] = sigmoidf_acc(pd + db[0]);
}

// =====================================================================
extern "C" void kernel_launch(void* const* d_in, const int* in_sizes, int n_in,
                              void* d_out, int out_size)
{
    const float* x    = (const float*)d_in[0];  // [256,1024,64]
    const float* kern = (const float*)d_in[1];  // [64,256]
    const float* rec  = (const float*)d_in[2];  // [64,256]
    const float* bias = (const float*)d_in[3];  // [256]
    const float* dw   = (const float*)d_in[4];  // [64,1]
    const float* db   = (const float*)d_in[5];  // [1]
    float* out = (float*)d_out;                 // [256,1024,1]

    lstm_xgemm<<<1024, 256>>>(x, kern, bias);
    lstm_recur<<<128, 256>>>(rec);
    lstm_head<<<(B_ * S_) / 8, 256>>>(dw, db, out);
}